// round 1
// baseline (speedup 1.0000x reference)
#include <cuda_runtime.h>
#include <math.h>

// ---------------------------------------------------------------------------
// Problem constants
// ---------------------------------------------------------------------------
#define NN        87381     // total nodes = (4^9-1)/3
#define NI        21845     // internal nodes (ids 0..21844)
#define LEAF_N    65536     // 4^8 leaves
#define LEAF_S    21845     // first leaf id
#define HDIM      256

// scratch offsets (floats)
#define OFF_XIOU  0u                          // NN  x 768
#define SZ_XIOU   (87381u*768u)
#define OFF_XF    (OFF_XIOU + SZ_XIOU)        // NI  x 256
#define SZ_XF     (21845u*256u)
#define OFF_Q     (OFF_XF + SZ_XF)            // NI  x 256
#define SZ_Q      (21845u*256u)
#define OFF_KK    (OFF_Q + SZ_Q)              // 65536 x 256
#define SZ_KK     (65536u*256u)
#define OFF_VV    (OFF_KK + SZ_KK)            // 65536 x 256
#define SZ_VV     (65536u*256u)
#define OFF_ATT   (OFF_VV + SZ_VV)            // 16384 x 256
#define SZ_ATT    (16384u*256u)
#define OFF_HATT  (OFF_ATT + SZ_ATT)          // 16384 x 256
#define SZ_HATT   (16384u*256u)
#define OFF_HIOU  (OFF_HATT + SZ_HATT)        // 16384 x 768
#define SZ_HIOU   (16384u*768u)
#define OFF_HF    (OFF_HIOU + SZ_HIOU)        // 16384 x 256
#define SZ_HF     (16384u*256u)
#define SCRATCH_FLOATS (OFF_HF + SZ_HF)

__device__ float g_scratch[SCRATCH_FLOATS];

// ---------------------------------------------------------------------------
// SGEMM: C[M,N] = A[M,256] @ B[256,N] + bias[N]
// 64x64 tile, k-tile 16, 256 threads, 4x4 per thread, float4 data paths.
// Requires: N % 64 == 0 (always 256 or 768 here). M arbitrary.
// ---------------------------------------------------------------------------
__global__ void sgemm_k256(const float* __restrict__ A,
                           const float* __restrict__ B,
                           const float* __restrict__ bias,
                           float* __restrict__ C,
                           int M, int N)
{
    __shared__ float As[16][64];
    __shared__ float Bs[16][68];   // 68 floats = 272B row: float4-aligned, padded

    const int tid = threadIdx.x;          // 0..255
    const int bm  = blockIdx.x * 64;
    const int bn  = blockIdx.y * 64;
    const int tx  = tid & 15;             // N direction
    const int ty  = tid >> 4;             // M direction

    const int arow  = tid >> 2;           // 0..63
    const int acol4 = (tid & 3) << 2;     // 0,4,8,12
    const int brow  = tid >> 4;           // 0..15
    const int bcol4 = (tid & 15) << 2;    // 0..60

    float acc[4][4];
    #pragma unroll
    for (int i = 0; i < 4; i++)
        #pragma unroll
        for (int j = 0; j < 4; j++) acc[i][j] = 0.f;

    const bool avalid = (bm + arow) < M;
    const float* Aptr = A + (size_t)(bm + arow) * 256 + acol4;
    const float* Bptr = B + (size_t)brow * N + bn + bcol4;

    for (int k0 = 0; k0 < 256; k0 += 16) {
        float4 av = avalid ? *(const float4*)(Aptr + k0)
                           : make_float4(0.f, 0.f, 0.f, 0.f);
        As[acol4 + 0][arow] = av.x;
        As[acol4 + 1][arow] = av.y;
        As[acol4 + 2][arow] = av.z;
        As[acol4 + 3][arow] = av.w;

        float4 bv = *(const float4*)(Bptr + (size_t)k0 * N);
        *(float4*)&Bs[brow][bcol4] = bv;

        __syncthreads();

        #pragma unroll
        for (int kk = 0; kk < 16; kk++) {
            float a[4], b[4];
            *(float4*)a = *(const float4*)&As[kk][ty << 2];
            *(float4*)b = *(const float4*)&Bs[kk][tx << 2];
            #pragma unroll
            for (int i = 0; i < 4; i++)
                #pragma unroll
                for (int j = 0; j < 4; j++)
                    acc[i][j] = fmaf(a[i], b[j], acc[i][j]);
        }
        __syncthreads();
    }

    float b0 = bias[bn + (tx << 2) + 0];
    float b1 = bias[bn + (tx << 2) + 1];
    float b2 = bias[bn + (tx << 2) + 2];
    float b3 = bias[bn + (tx << 2) + 3];

    #pragma unroll
    for (int i = 0; i < 4; i++) {
        int row = bm + (ty << 2) + i;
        if (row < M) {
            float4 r;
            r.x = acc[i][0] + b0;
            r.y = acc[i][1] + b1;
            r.z = acc[i][2] + b2;
            r.w = acc[i][3] + b3;
            *(float4*)&C[(size_t)row * N + bn + (tx << 2)] = r;
        }
    }
}

// ---------------------------------------------------------------------------
// Attention: one block per node, warp per head (8 heads x 32 dims = 256 thr).
// logits over K=4 children via warp butterfly reduce, softmax, weighted V sum.
// ---------------------------------------------------------------------------
__global__ void attn_kernel(const float* __restrict__ q,   // [NI,256] node-id indexed
                            const float* __restrict__ kk,  // [4n,256] child-local rows
                            const float* __restrict__ vv,  // [4n,256]
                            float* __restrict__ out,       // [n,256]
                            int s0)
{
    const int node = blockIdx.x;
    const int d    = threadIdx.x;            // head = d>>5, lane = d&31
    const float qv = q[(size_t)(s0 + node) * 256 + d];

    float logit[4];
    #pragma unroll
    for (int k = 0; k < 4; k++) {
        float p = qv * kk[((size_t)(node * 4 + k)) * 256 + d];
        #pragma unroll
        for (int off = 16; off > 0; off >>= 1)
            p += __shfl_xor_sync(0xffffffffu, p, off);
        logit[k] = p * 0.1767766952966369f;  // 1/sqrt(32)
    }
    float mx = fmaxf(fmaxf(logit[0], logit[1]), fmaxf(logit[2], logit[3]));
    float e[4];
    float s = 0.f;
    #pragma unroll
    for (int k = 0; k < 4; k++) { e[k] = expf(logit[k] - mx); s += e[k]; }
    const float inv = 1.f / s;

    float o = 0.f;
    #pragma unroll
    for (int k = 0; k < 4; k++)
        o += (e[k] * inv) * vv[((size_t)(node * 4 + k)) * 256 + d];
    out[(size_t)node * 256 + d] = o;
}

// ---------------------------------------------------------------------------
// Elementwise kernels
// ---------------------------------------------------------------------------
__device__ __forceinline__ float sigm(float x) { return 1.f / (1.f + expf(-x)); }

__global__ void leaf_kernel(const float* __restrict__ xiou,
                            float* __restrict__ h_out,
                            float* __restrict__ c_out)
{
    const size_t node = LEAF_S + blockIdx.x;
    const int j = threadIdx.x;
    const float ig = xiou[node * 768 + j];
    const float og = xiou[node * 768 + 256 + j];
    const float ug = xiou[node * 768 + 512 + j];
    const float c  = sigm(ig) * tanhf(ug);
    const float h  = sigm(og) * tanhf(c);
    h_out[node * 256 + j] = h;
    c_out[node * 256 + j] = c;
}

__global__ void combine_kernel(const float* __restrict__ xiou,
                               const float* __restrict__ xf,
                               const float* __restrict__ hiou,
                               const float* __restrict__ hf,
                               float* __restrict__ h_out,
                               float* __restrict__ c_out,
                               int s0, int child_start)
{
    const int i = blockIdx.x;          // local node index
    const int j = threadIdx.x;
    const size_t gr = (size_t)(s0 + i);

    const float ig = xiou[gr * 768 + j]        + hiou[(size_t)i * 768 + j];
    const float og = xiou[gr * 768 + 256 + j]  + hiou[(size_t)i * 768 + 256 + j];
    const float ug = xiou[gr * 768 + 512 + j]  + hiou[(size_t)i * 768 + 512 + j];
    const float f  = sigm(xf[gr * 256 + j] + hf[(size_t)i * 256 + j]);

    const size_t cb = (size_t)(child_start + i * 4) * 256 + j;
    const float csum = c_out[cb] + c_out[cb + 256] + c_out[cb + 512] + c_out[cb + 768];

    const float c = sigm(ig) * tanhf(ug) + f * csum;
    const float h = sigm(og) * tanhf(c);
    h_out[gr * 256 + j] = h;
    c_out[gr * 256 + j] = c;
}

// ---------------------------------------------------------------------------
// Launch
// ---------------------------------------------------------------------------
extern "C" void kernel_launch(void* const* d_in, const int* in_sizes, int n_in,
                              void* d_out, int out_size)
{
    const float* x      = (const float*)d_in[0];
    const float* W_iou  = (const float*)d_in[1];
    const float* b_iou  = (const float*)d_in[2];
    const float* W_f    = (const float*)d_in[3];
    const float* b_f    = (const float*)d_in[4];
    const float* Wq     = (const float*)d_in[5];
    const float* bq     = (const float*)d_in[6];
    const float* Wk     = (const float*)d_in[7];
    const float* bk     = (const float*)d_in[8];
    const float* Wv     = (const float*)d_in[9];
    const float* bv     = (const float*)d_in[10];
    const float* Wl     = (const float*)d_in[11];
    const float* bl     = (const float*)d_in[12];
    const float* Uiou_w = (const float*)d_in[13];
    const float* Uiou_b = (const float*)d_in[14];
    const float* Uf_w   = (const float*)d_in[15];
    const float* Uf_b   = (const float*)d_in[16];

    float* h_out = (float*)d_out;
    float* c_out = h_out + (size_t)NN * 256;

    float* scratch = nullptr;
    cudaGetSymbolAddress((void**)&scratch, g_scratch);
    float* g_xiou = scratch + OFF_XIOU;
    float* g_xf   = scratch + OFF_XF;
    float* g_q    = scratch + OFF_Q;
    float* g_kk   = scratch + OFF_KK;
    float* g_vv   = scratch + OFF_VV;
    float* g_att  = scratch + OFF_ATT;
    float* g_hatt = scratch + OFF_HATT;
    float* g_hiou = scratch + OFF_HIOU;
    float* g_hf   = scratch + OFF_HF;

    // ---- precompute (fully parallel GEMMs) ----
    sgemm_k256<<<dim3((NN + 63) / 64, 12), 256>>>(x, W_iou, b_iou, g_xiou, NN, 768);
    sgemm_k256<<<dim3((NI + 63) / 64, 4),  256>>>(x, W_f,   b_f,   g_xf,   NI, 256);
    sgemm_k256<<<dim3((NI + 63) / 64, 4),  256>>>(x, Wq,    bq,    g_q,    NI, 256);

    // ---- leaf level (pure elementwise) ----
    leaf_kernel<<<LEAF_N, 256>>>(g_xiou, h_out, c_out);

    // ---- internal levels, bottom-up ----
    const int starts[9] = {0, 1, 5, 21, 85, 341, 1365, 5461, 21845};
    for (int l = 7; l >= 0; l--) {
        const int n  = 1 << (2 * l);
        const int s0 = starts[l];
        const int cs = starts[l + 1];
        const int nK = n * 4;
        const float* ch = h_out + (size_t)cs * 256;

        sgemm_k256<<<dim3((nK + 63) / 64, 4),  256>>>(ch,     Wk,     bk,     g_kk,   nK, 256);
        sgemm_k256<<<dim3((nK + 63) / 64, 4),  256>>>(ch,     Wv,     bv,     g_vv,   nK, 256);
        attn_kernel<<<n, 256>>>(g_q, g_kk, g_vv, g_att, s0);
        sgemm_k256<<<dim3((n + 63) / 64, 4),   256>>>(g_att,  Wl,     bl,     g_hatt, n, 256);
        sgemm_k256<<<dim3((n + 63) / 64, 12),  256>>>(g_hatt, Uiou_w, Uiou_b, g_hiou, n, 768);
        sgemm_k256<<<dim3((n + 63) / 64, 4),   256>>>(g_hatt, Uf_w,   Uf_b,   g_hf,   n, 256);
        combine_kernel<<<n, 256>>>(g_xiou, g_xf, g_hiou, g_hf, h_out, c_out, s0, cs);
    }
}

// round 3
// speedup vs baseline: 2.1745x; 2.1745x over previous
#include <cuda_runtime.h>
#include <cuda_bf16.h>
#include <math.h>
#include <stdint.h>

// ---------------------------------------------------------------------------
// Problem constants
// ---------------------------------------------------------------------------
#define NN        87381     // total nodes = (4^9-1)/3
#define NI        21845     // internal nodes
#define LEAF_N    65536
#define LEAF_S    21845

// ---------------------------------------------------------------------------
// Device scratch (static — no allocation allowed)
// ---------------------------------------------------------------------------
__device__ float g_xiou[NN * 768];
__device__ float g_xf[NI * 256];
__device__ float g_q[NI * 256];
__device__ float g_kk[65536 * 256];
__device__ float g_vv[65536 * 256];
__device__ float g_hiou[16384 * 768];
__device__ float g_hf[16384 * 256];

__device__ __nv_bfloat16 g_xhi[NN * 256],    g_xlo[NN * 256];
__device__ __nv_bfloat16 g_hhi[NN * 256],    g_hlo[NN * 256];
__device__ __nv_bfloat16 g_atthi[16384 * 256],  g_attlo[16384 * 256];
__device__ __nv_bfloat16 g_hatthi[16384 * 256], g_hattlo[16384 * 256];

// transposed + bf16 hi/lo split weights: rows = output cols (N), 256 K each
#define WT_IOU  0
#define WT_F    768
#define WT_Q    1024
#define WT_K    1280
#define WT_V    1536
#define WT_L    1792
#define WT_UIOU 2048
#define WT_UF   2816
__device__ __nv_bfloat16 g_wthi[3072 * 256];
__device__ __nv_bfloat16 g_wtlo[3072 * 256];

// ---------------------------------------------------------------------------
// PTX helpers (all sm_80+ — safe for plain sm_103 target)
// ---------------------------------------------------------------------------
__device__ __forceinline__ uint32_t s2u(const void* p) {
    uint32_t a;
    asm("{ .reg .u64 t; cvta.to.shared.u64 t, %1; cvt.u32.u64 %0, t; }"
        : "=r"(a) : "l"(p));
    return a;
}
__device__ __forceinline__ void cpa16(uint32_t dst, const void* src, int nbytes) {
    asm volatile("cp.async.cg.shared.global [%0], [%1], 16, %2;"
                 :: "r"(dst), "l"(src), "r"(nbytes) : "memory");
}
__device__ __forceinline__ void cpa_commit() {
    asm volatile("cp.async.commit_group;" ::: "memory");
}
__device__ __forceinline__ void ldm4(uint32_t* r, uint32_t addr) {
    asm volatile("ldmatrix.sync.aligned.m8n8.x4.shared.b16 {%0,%1,%2,%3}, [%4];"
                 : "=r"(r[0]), "=r"(r[1]), "=r"(r[2]), "=r"(r[3]) : "r"(addr));
}
__device__ __forceinline__ void mma16816(float* c, const uint32_t* a, const uint32_t* b) {
    asm volatile(
        "mma.sync.aligned.m16n8k16.row.col.f32.bf16.bf16.f32 "
        "{%0,%1,%2,%3}, {%4,%5,%6,%7}, {%8,%9}, {%0,%1,%2,%3};"
        : "+f"(c[0]), "+f"(c[1]), "+f"(c[2]), "+f"(c[3])
        : "r"(a[0]), "r"(a[1]), "r"(a[2]), "r"(a[3]), "r"(b[0]), "r"(b[1]));
}
__device__ __forceinline__ uint32_t swadr(uint32_t base, int row, int gran) {
    return base + row * 128 + ((gran ^ (row & 7)) << 4);
}
__device__ __forceinline__ uint32_t packbf(__nv_bfloat16 a, __nv_bfloat16 b) {
    return ((uint32_t)__bfloat16_as_ushort(b) << 16) | __bfloat16_as_ushort(a);
}
__device__ __forceinline__ void wsplit(__nv_bfloat16* hi, __nv_bfloat16* lo,
                                       size_t idx, float v) {
    __nv_bfloat16 h = __float2bfloat16(v);
    hi[idx] = h;
    lo[idx] = __float2bfloat16(v - __bfloat162float(h));
}

// ---------------------------------------------------------------------------
// bf16 HMMA GEMM:  C[M, Ntot] = A[M,256] @ Wt^T + bias
//   A given as bf16 hi/lo [M,256]; Wt as bf16 hi/lo [Ntot,256] (pre-transposed)
//   D = Ahi*Bhi + Ahi*Blo + Alo*Bhi  (fp32 accumulate)
//   CTA tile 128x128, 8 warps (2m x 4n), warp tile 64x32, k-chunk 64 (x4),
//   cp.async double buffer, XOR-swizzled smem, ldmatrix fragments.
// ---------------------------------------------------------------------------
#define STG    65536
#define OA_HI  0
#define OA_LO  16384
#define OB_HI  32768
#define OB_LO  49152
#define GSMEM  (2 * STG)   // 131072 bytes

__global__ void __launch_bounds__(256, 1)
gemm_bf16(const __nv_bfloat16* __restrict__ Ahi,
          const __nv_bfloat16* __restrict__ Alo,
          const __nv_bfloat16* __restrict__ Bhi,
          const __nv_bfloat16* __restrict__ Blo,
          const float* __restrict__ bias,
          float* __restrict__ C,
          __nv_bfloat16* __restrict__ Chi,
          __nv_bfloat16* __restrict__ Clo,
          int M, int Ntot)
{
    extern __shared__ char smem[];
    const uint32_t sb = s2u(smem);
    const int tid  = threadIdx.x;
    const int lane = tid & 31;
    const int wid  = tid >> 5;
    const int wm   = wid & 1;       // 0..1
    const int wn   = wid >> 1;      // 0..3
    const int bm   = blockIdx.x * 128;
    const int n0   = blockIdx.y * 128;

    float acc[4][4][4];
    #pragma unroll
    for (int a = 0; a < 4; a++)
        #pragma unroll
        for (int b = 0; b < 4; b++)
            #pragma unroll
            for (int c = 0; c < 4; c++) acc[a][b][c] = 0.f;

    // ---- async stage of one k-chunk (64 k) into given stage buffer
    auto stage_chunk = [&](uint32_t sa, int kc) {
        #pragma unroll
        for (int t = 0; t < 4; t++) {
            int i = tid + t * 256;           // 0..1023
            int row = i >> 3, g = i & 7;
            uint32_t d = row * 128 + ((g ^ (row & 7)) << 4);
            int  arow = bm + row;
            int  av   = arow < M ? 16 : 0;
            size_t as = (size_t)(arow < M ? arow : 0) * 256 + kc * 64 + g * 8;
            size_t bs = (size_t)(n0 + row) * 256 + kc * 64 + g * 8;
            cpa16(sa + OA_HI + d, Ahi + as, av);
            cpa16(sa + OA_LO + d, Alo + as, av);
            cpa16(sa + OB_HI + d, Bhi + bs, 16);
            cpa16(sa + OB_LO + d, Blo + bs, 16);
        }
        cpa_commit();
    };

    stage_chunk(sb, 0);

    for (int kc = 0; kc < 4; kc++) {
        if (kc < 3) {
            stage_chunk(sb + ((kc + 1) & 1) * STG, kc + 1);
            asm volatile("cp.async.wait_group 1;" ::: "memory");
        } else {
            asm volatile("cp.async.wait_group 0;" ::: "memory");
        }
        __syncthreads();

        const uint32_t sa = sb + (kc & 1) * STG;
        #pragma unroll
        for (int ks = 0; ks < 4; ks++) {
            uint32_t ahi[4][4], alo[4][4], bh[2][4], bl[2][4];
            #pragma unroll
            for (int mi = 0; mi < 4; mi++) {
                int rA = wm * 64 + mi * 16 + (lane & 15);
                int gA = 2 * ks + (lane >> 4);
                ldm4(ahi[mi], swadr(sa + OA_HI, rA, gA));
                ldm4(alo[mi], swadr(sa + OA_LO, rA, gA));
            }
            #pragma unroll
            for (int bi = 0; bi < 2; bi++) {
                int rB = wn * 32 + bi * 16 + (lane & 7) + ((lane >> 4) << 3);
                int gB = 2 * ks + ((lane >> 3) & 1);
                ldm4(bh[bi], swadr(sa + OB_HI, rB, gB));
                ldm4(bl[bi], swadr(sa + OB_LO, rB, gB));
            }
            #pragma unroll
            for (int mi = 0; mi < 4; mi++)
                #pragma unroll
                for (int nf = 0; nf < 4; nf++)
                    mma16816(acc[mi][nf], ahi[mi], &bh[nf >> 1][(nf & 1) * 2]);
            #pragma unroll
            for (int mi = 0; mi < 4; mi++)
                #pragma unroll
                for (int nf = 0; nf < 4; nf++)
                    mma16816(acc[mi][nf], ahi[mi], &bl[nf >> 1][(nf & 1) * 2]);
            #pragma unroll
            for (int mi = 0; mi < 4; mi++)
                #pragma unroll
                for (int nf = 0; nf < 4; nf++)
                    mma16816(acc[mi][nf], alo[mi], &bh[nf >> 1][(nf & 1) * 2]);
        }
        __syncthreads();
    }

    // ---- epilogue
    #pragma unroll
    for (int mi = 0; mi < 4; mi++) {
        #pragma unroll
        for (int nf = 0; nf < 4; nf++) {
            int r0  = bm + wm * 64 + mi * 16 + (lane >> 2);
            int col = n0 + wn * 32 + nf * 8 + ((lane & 3) << 1);
            float2 b2 = *(const float2*)&bias[col];
            float v0 = acc[mi][nf][0] + b2.x;
            float v1 = acc[mi][nf][1] + b2.y;
            float v2 = acc[mi][nf][2] + b2.x;
            float v3 = acc[mi][nf][3] + b2.y;
            if (r0 < M) {
                size_t o = (size_t)r0 * Ntot + col;
                if (C) *(float2*)&C[o] = make_float2(v0, v1);
                if (Chi) {
                    __nv_bfloat16 h0 = __float2bfloat16(v0);
                    __nv_bfloat16 h1 = __float2bfloat16(v1);
                    *(uint32_t*)&Chi[o] = packbf(h0, h1);
                    *(uint32_t*)&Clo[o] = packbf(
                        __float2bfloat16(v0 - __bfloat162float(h0)),
                        __float2bfloat16(v1 - __bfloat162float(h1)));
                }
            }
            if (r0 + 8 < M) {
                size_t o = (size_t)(r0 + 8) * Ntot + col;
                if (C) *(float2*)&C[o] = make_float2(v2, v3);
                if (Chi) {
                    __nv_bfloat16 h2 = __float2bfloat16(v2);
                    __nv_bfloat16 h3 = __float2bfloat16(v3);
                    *(uint32_t*)&Chi[o] = packbf(h2, h3);
                    *(uint32_t*)&Clo[o] = packbf(
                        __float2bfloat16(v2 - __bfloat162float(h2)),
                        __float2bfloat16(v3 - __bfloat162float(h3)));
                }
            }
        }
    }
}

// ---------------------------------------------------------------------------
// Weight prep: transpose W[256, N] -> Wt[N, 256], split into bf16 hi/lo
// ---------------------------------------------------------------------------
__global__ void prep_w(const float* __restrict__ W,
                       __nv_bfloat16* __restrict__ hi,
                       __nv_bfloat16* __restrict__ lo, int N)
{
    int n = blockIdx.x;
    int k = threadIdx.x;
    float v = W[(size_t)k * N + n];
    __nv_bfloat16 h = __float2bfloat16(v);
    hi[(size_t)n * 256 + k] = h;
    lo[(size_t)n * 256 + k] = __float2bfloat16(v - __bfloat162float(h));
}

// ---------------------------------------------------------------------------
// split x into bf16 hi/lo (float4 vectorized)
// ---------------------------------------------------------------------------
__global__ void split_x(const float* __restrict__ x,
                        __nv_bfloat16* __restrict__ hi,
                        __nv_bfloat16* __restrict__ lo, int total4)
{
    int i = blockIdx.x * blockDim.x + threadIdx.x;
    if (i >= total4) return;
    float4 v = *(const float4*)&x[i * 4];
    __nv_bfloat16 h0 = __float2bfloat16(v.x), h1 = __float2bfloat16(v.y);
    __nv_bfloat16 h2 = __float2bfloat16(v.z), h3 = __float2bfloat16(v.w);
    uint2 hp, lp;
    hp.x = packbf(h0, h1); hp.y = packbf(h2, h3);
    lp.x = packbf(__float2bfloat16(v.x - __bfloat162float(h0)),
                  __float2bfloat16(v.y - __bfloat162float(h1)));
    lp.y = packbf(__float2bfloat16(v.z - __bfloat162float(h2)),
                  __float2bfloat16(v.w - __bfloat162float(h3)));
    *(uint2*)&hi[i * 4] = hp;
    *(uint2*)&lo[i * 4] = lp;
}

// ---------------------------------------------------------------------------
// Attention: one block per node, warp per head; emits bf16 hi/lo split
// ---------------------------------------------------------------------------
__global__ void attn_kernel(const float* __restrict__ q,
                            const float* __restrict__ kk,
                            const float* __restrict__ vv,
                            __nv_bfloat16* __restrict__ ohi,
                            __nv_bfloat16* __restrict__ olo,
                            int s0)
{
    const int node = blockIdx.x;
    const int d = threadIdx.x;
    const float qv = q[(size_t)(s0 + node) * 256 + d];

    float logit[4];
    #pragma unroll
    for (int k = 0; k < 4; k++) {
        float p = qv * kk[((size_t)(node * 4 + k)) * 256 + d];
        #pragma unroll
        for (int off = 16; off > 0; off >>= 1)
            p += __shfl_xor_sync(0xffffffffu, p, off);
        logit[k] = p * 0.1767766952966369f;   // 1/sqrt(32)
    }
    float mx = fmaxf(fmaxf(logit[0], logit[1]), fmaxf(logit[2], logit[3]));
    float e[4];
    float s = 0.f;
    #pragma unroll
    for (int k = 0; k < 4; k++) { e[k] = expf(logit[k] - mx); s += e[k]; }
    const float inv = 1.f / s;

    float o = 0.f;
    #pragma unroll
    for (int k = 0; k < 4; k++)
        o += (e[k] * inv) * vv[((size_t)(node * 4 + k)) * 256 + d];
    wsplit(ohi, olo, (size_t)node * 256 + d, o);
}

// ---------------------------------------------------------------------------
// Elementwise
// ---------------------------------------------------------------------------
__device__ __forceinline__ float sigm(float x) { return 1.f / (1.f + expf(-x)); }

__global__ void leaf_kernel(const float* __restrict__ xiou,
                            float* __restrict__ h_out,
                            float* __restrict__ c_out,
                            __nv_bfloat16* __restrict__ hhi,
                            __nv_bfloat16* __restrict__ hlo)
{
    const size_t node = LEAF_S + (size_t)blockIdx.x * 4 + (threadIdx.x >> 6);
    const int j = (threadIdx.x & 63) << 2;
    const float4 i4 = *(const float4*)&xiou[node * 768 + j];
    const float4 o4 = *(const float4*)&xiou[node * 768 + 256 + j];
    const float4 u4 = *(const float4*)&xiou[node * 768 + 512 + j];
    float4 c, h;
    c.x = sigm(i4.x) * tanhf(u4.x); h.x = sigm(o4.x) * tanhf(c.x);
    c.y = sigm(i4.y) * tanhf(u4.y); h.y = sigm(o4.y) * tanhf(c.y);
    c.z = sigm(i4.z) * tanhf(u4.z); h.z = sigm(o4.z) * tanhf(c.z);
    c.w = sigm(i4.w) * tanhf(u4.w); h.w = sigm(o4.w) * tanhf(c.w);
    *(float4*)&h_out[node * 256 + j] = h;
    *(float4*)&c_out[node * 256 + j] = c;
    size_t o = node * 256 + j;
    wsplit(hhi, hlo, o + 0, h.x);
    wsplit(hhi, hlo, o + 1, h.y);
    wsplit(hhi, hlo, o + 2, h.z);
    wsplit(hhi, hlo, o + 3, h.w);
}

__global__ void combine_kernel(const float* __restrict__ xiou,
                               const float* __restrict__ xf,
                               const float* __restrict__ hiou,
                               const float* __restrict__ hf,
                               float* __restrict__ h_out,
                               float* __restrict__ c_out,
                               __nv_bfloat16* __restrict__ hhi,
                               __nv_bfloat16* __restrict__ hlo,
                               int s0, int child_start)
{
    const int i = blockIdx.x;
    const int j = threadIdx.x;
    const size_t gr = (size_t)(s0 + i);

    const float ig = xiou[gr * 768 + j]       + hiou[(size_t)i * 768 + j];
    const float og = xiou[gr * 768 + 256 + j] + hiou[(size_t)i * 768 + 256 + j];
    const float ug = xiou[gr * 768 + 512 + j] + hiou[(size_t)i * 768 + 512 + j];
    const float f  = sigm(xf[gr * 256 + j] + hf[(size_t)i * 256 + j]);

    const size_t cb = (size_t)(child_start + i * 4) * 256 + j;
    const float csum = c_out[cb] + c_out[cb + 256] + c_out[cb + 512] + c_out[cb + 768];

    const float c = sigm(ig) * tanhf(ug) + f * csum;
    const float h = sigm(og) * tanhf(c);
    h_out[gr * 256 + j] = h;
    c_out[gr * 256 + j] = c;
    wsplit(hhi, hlo, gr * 256 + j, h);
}

// ---------------------------------------------------------------------------
// Launch
// ---------------------------------------------------------------------------
extern "C" void kernel_launch(void* const* d_in, const int* in_sizes, int n_in,
                              void* d_out, int out_size)
{
    const float* x      = (const float*)d_in[0];
    const float* W_iou  = (const float*)d_in[1];
    const float* b_iou  = (const float*)d_in[2];
    const float* W_f    = (const float*)d_in[3];
    const float* b_f    = (const float*)d_in[4];
    const float* Wq     = (const float*)d_in[5];
    const float* bq     = (const float*)d_in[6];
    const float* Wk     = (const float*)d_in[7];
    const float* bk     = (const float*)d_in[8];
    const float* Wv     = (const float*)d_in[9];
    const float* bv     = (const float*)d_in[10];
    const float* Wl     = (const float*)d_in[11];
    const float* bl     = (const float*)d_in[12];
    const float* Uiou_w = (const float*)d_in[13];
    const float* Uiou_b = (const float*)d_in[14];
    const float* Uf_w   = (const float*)d_in[15];
    const float* Uf_b   = (const float*)d_in[16];

    float* h_out = (float*)d_out;
    float* c_out = h_out + (size_t)NN * 256;

    // resolve device symbols
    float *xiou, *xf, *q, *kk, *vv, *hiou, *hf;
    __nv_bfloat16 *xhi, *xlo, *hhi, *hlo, *atthi, *attlo, *hatthi, *hattlo, *wthi, *wtlo;
    cudaGetSymbolAddress((void**)&xiou, g_xiou);
    cudaGetSymbolAddress((void**)&xf, g_xf);
    cudaGetSymbolAddress((void**)&q, g_q);
    cudaGetSymbolAddress((void**)&kk, g_kk);
    cudaGetSymbolAddress((void**)&vv, g_vv);
    cudaGetSymbolAddress((void**)&hiou, g_hiou);
    cudaGetSymbolAddress((void**)&hf, g_hf);
    cudaGetSymbolAddress((void**)&xhi, g_xhi);
    cudaGetSymbolAddress((void**)&xlo, g_xlo);
    cudaGetSymbolAddress((void**)&hhi, g_hhi);
    cudaGetSymbolAddress((void**)&hlo, g_hlo);
    cudaGetSymbolAddress((void**)&atthi, g_atthi);
    cudaGetSymbolAddress((void**)&attlo, g_attlo);
    cudaGetSymbolAddress((void**)&hatthi, g_hatthi);
    cudaGetSymbolAddress((void**)&hattlo, g_hattlo);
    cudaGetSymbolAddress((void**)&wthi, g_wthi);
    cudaGetSymbolAddress((void**)&wtlo, g_wtlo);

    cudaFuncSetAttribute(gemm_bf16, cudaFuncAttributeMaxDynamicSharedMemorySize, GSMEM);

    auto GEMM = [&](const __nv_bfloat16* Ahi, const __nv_bfloat16* Alo, int wt,
                    const float* bias, float* C, __nv_bfloat16* Chi, __nv_bfloat16* Clo,
                    int M, int Ntot) {
        dim3 grid((M + 127) / 128, Ntot / 128);
        gemm_bf16<<<grid, 256, GSMEM>>>(Ahi, Alo,
                                        wthi + (size_t)wt * 256, wtlo + (size_t)wt * 256,
                                        bias, C, Chi, Clo, M, Ntot);
    };

    // ---- weight prep ----
    prep_w<<<768, 256>>>(W_iou,  wthi + WT_IOU  * 256, wtlo + WT_IOU  * 256, 768);
    prep_w<<<256, 256>>>(W_f,    wthi + WT_F    * 256, wtlo + WT_F    * 256, 256);
    prep_w<<<256, 256>>>(Wq,     wthi + WT_Q    * 256, wtlo + WT_Q    * 256, 256);
    prep_w<<<256, 256>>>(Wk,     wthi + WT_K    * 256, wtlo + WT_K    * 256, 256);
    prep_w<<<256, 256>>>(Wv,     wthi + WT_V    * 256, wtlo + WT_V    * 256, 256);
    prep_w<<<256, 256>>>(Wl,     wthi + WT_L    * 256, wtlo + WT_L    * 256, 256);
    prep_w<<<768, 256>>>(Uiou_w, wthi + WT_UIOU * 256, wtlo + WT_UIOU * 256, 768);
    prep_w<<<256, 256>>>(Uf_w,   wthi + WT_UF   * 256, wtlo + WT_UF   * 256, 256);

    // ---- split x, precompute GEMMs ----
    const int tot4 = NN * 256 / 4;
    split_x<<<(tot4 + 255) / 256, 256>>>(x, xhi, xlo, tot4);
    GEMM(xhi, xlo, WT_IOU, b_iou, xiou, nullptr, nullptr, NN, 768);
    GEMM(xhi, xlo, WT_F,   b_f,   xf,   nullptr, nullptr, NI, 256);
    GEMM(xhi, xlo, WT_Q,   bq,    q,    nullptr, nullptr, NI, 256);

    // ---- leaf level ----
    leaf_kernel<<<LEAF_N / 4, 256>>>(xiou, h_out, c_out, hhi, hlo);

    // ---- internal levels, bottom-up ----
    const int starts[9] = {0, 1, 5, 21, 85, 341, 1365, 5461, 21845};
    for (int l = 7; l >= 0; l--) {
        const int n  = 1 << (2 * l);
        const int s0 = starts[l];
        const int cs = starts[l + 1];
        const int nK = n * 4;
        const __nv_bfloat16* chhi = hhi + (size_t)cs * 256;
        const __nv_bfloat16* chlo = hlo + (size_t)cs * 256;

        GEMM(chhi, chlo, WT_K, bk, kk, nullptr, nullptr, nK, 256);
        GEMM(chhi, chlo, WT_V, bv, vv, nullptr, nullptr, nK, 256);
        attn_kernel<<<n, 256>>>(q, kk, vv, atthi, attlo, s0);
        GEMM(atthi, attlo, WT_L, bl, nullptr, hatthi, hattlo, n, 256);
        GEMM(hatthi, hattlo, WT_UIOU, Uiou_b, hiou, nullptr, nullptr, n, 768);
        GEMM(hatthi, hattlo, WT_UF,   Uf_b,   hf,   nullptr, nullptr, n, 256);
        combine_kernel<<<n, 256>>>(xiou, xf, hiou, hf, h_out, c_out, hhi, hlo, s0, cs);
    }
}

// round 5
// speedup vs baseline: 2.9605x; 1.3615x over previous
#include <cuda_runtime.h>
#include <cuda_fp16.h>
#include <math.h>
#include <stdint.h>

// ---------------------------------------------------------------------------
// Problem constants
// ---------------------------------------------------------------------------
#define NN        87381     // total nodes = (4^9-1)/3
#define NI        21845     // internal nodes
#define LEAF_N    65536
#define LEAF_S    21845

// ---------------------------------------------------------------------------
// Device scratch (static — no allocation allowed)
// ---------------------------------------------------------------------------
__device__ float  g_xiou[NN * 768];          // iou preactivations (fp32)
__device__ float  g_xfq[NI * 512];           // cols 0-255: x_f, 256-511: q
__device__ float  g_hu[16384 * 1024];        // cols 0-767: h_iou, 768-1023: h_f
__device__ __half g_kkvv[65536 * 512];       // cols 0-255: k, 256-511: v
__device__ __half g_att[16384 * 256];
__device__ __half g_hatt[16384 * 256];
__device__ __half g_xh[NN * 256];            // x as fp16
__device__ __half g_hh[NN * 256];            // h as fp16

// weight rows (transposed, fp16 hi/lo). row index == bias index.
#define WT_IOU  0       // 768 rows
#define WT_FQ   768     // 512 rows (f, q)
#define WT_KV   1280    // 512 rows (k, v)
#define WT_L    1792    // 256 rows
#define WT_U    2048    // 1024 rows (uiou, uf)
__device__ __half g_wthi[3072 * 256];
__device__ __half g_wtlo[3072 * 256];
__device__ float  g_bias[3072];

// ---------------------------------------------------------------------------
// PTX helpers (sm_80+ — safe for plain sm_103 ptxas target)
// ---------------------------------------------------------------------------
__device__ __forceinline__ uint32_t s2u(const void* p) {
    uint32_t a;
    asm("{ .reg .u64 t; cvta.to.shared.u64 t, %1; cvt.u32.u64 %0, t; }"
        : "=r"(a) : "l"(p));
    return a;
}
__device__ __forceinline__ void cpa16(uint32_t dst, const void* src, int nbytes) {
    asm volatile("cp.async.cg.shared.global [%0], [%1], 16, %2;"
                 :: "r"(dst), "l"(src), "r"(nbytes) : "memory");
}
__device__ __forceinline__ void cpa_commit() {
    asm volatile("cp.async.commit_group;" ::: "memory");
}
__device__ __forceinline__ void ldm4(uint32_t* r, uint32_t addr) {
    asm volatile("ldmatrix.sync.aligned.m8n8.x4.shared.b16 {%0,%1,%2,%3}, [%4];"
                 : "=r"(r[0]), "=r"(r[1]), "=r"(r[2]), "=r"(r[3]) : "r"(addr));
}
__device__ __forceinline__ void mma16816(float* c, const uint32_t* a, const uint32_t* b) {
    asm volatile(
        "mma.sync.aligned.m16n8k16.row.col.f32.f16.f16.f32 "
        "{%0,%1,%2,%3}, {%4,%5,%6,%7}, {%8,%9}, {%0,%1,%2,%3};"
        : "+f"(c[0]), "+f"(c[1]), "+f"(c[2]), "+f"(c[3])
        : "r"(a[0]), "r"(a[1]), "r"(a[2]), "r"(a[3]), "r"(b[0]), "r"(b[1]));
}
__device__ __forceinline__ uint32_t swadr(uint32_t base, int row, int gran) {
    return base + row * 128 + ((gran ^ (row & 7)) << 4);
}
__device__ __forceinline__ uint32_t packh(__half a, __half b) {
    return ((uint32_t)__half_as_ushort(b) << 16) | __half_as_ushort(a);
}

// ---------------------------------------------------------------------------
// fp16 HMMA GEMM:  C[M, Ntot] = A[M,256] @ Wt^T + bias
//   A fp16 [M,256]; Wt fp16 hi/lo [Ntot,256].  D = A*Bhi + A*Blo (fp32 acc).
//   CTA tile 128x128, 8 warps (2m x 4n), warp 64x32, k-chunk 64 x4, 3-stage
//   cp.async pipeline, XOR-swizzled smem, ldmatrix.
// ---------------------------------------------------------------------------
#define STG    49152
#define OA     0
#define OBH    16384
#define OBL    32768
#define GSMEM  (3 * STG)   // 147456 bytes

__global__ void __launch_bounds__(256, 1)
gemm_f16(const __half* __restrict__ A,
         const __half* __restrict__ Bhi,
         const __half* __restrict__ Blo,
         const float* __restrict__ bias,
         float* __restrict__ C,
         __half* __restrict__ Ch,
         int M, int Ntot)
{
    extern __shared__ char smem[];
    const uint32_t sb = s2u(smem);
    const int tid  = threadIdx.x;
    const int lane = tid & 31;
    const int wid  = tid >> 5;
    const int wm   = wid & 1;
    const int wn   = wid >> 1;
    const int bm   = blockIdx.x * 128;
    const int n0   = blockIdx.y * 128;

    float acc[4][4][4];
    #pragma unroll
    for (int a = 0; a < 4; a++)
        #pragma unroll
        for (int b = 0; b < 4; b++)
            #pragma unroll
            for (int c = 0; c < 4; c++) acc[a][b][c] = 0.f;

    auto stage_chunk = [&](int kc) {
        uint32_t sa = sb + (kc % 3) * STG;
        #pragma unroll
        for (int t = 0; t < 4; t++) {
            int i = tid + t * 256;            // 0..1023
            int row = i >> 3, g = i & 7;
            uint32_t d = row * 128 + ((g ^ (row & 7)) << 4);
            int  arow = bm + row;
            int  av   = arow < M ? 16 : 0;
            size_t as = (size_t)(arow < M ? arow : 0) * 256 + kc * 64 + g * 8;
            size_t bs = (size_t)(n0 + row) * 256 + kc * 64 + g * 8;
            cpa16(sa + OA  + d, A + as, av);
            cpa16(sa + OBH + d, Bhi + bs, 16);
            cpa16(sa + OBL + d, Blo + bs, 16);
        }
        cpa_commit();
    };

    stage_chunk(0);
    stage_chunk(1);

    for (int kc = 0; kc < 4; kc++) {
        if (kc < 3)
            asm volatile("cp.async.wait_group 1;" ::: "memory");
        else
            asm volatile("cp.async.wait_group 0;" ::: "memory");
        __syncthreads();
        if (kc + 2 < 4) stage_chunk(kc + 2);

        const uint32_t sa = sb + (kc % 3) * STG;
        #pragma unroll
        for (int ks = 0; ks < 4; ks++) {
            uint32_t af[4][4], bh[2][4], bl[2][4];
            #pragma unroll
            for (int mi = 0; mi < 4; mi++) {
                int rA = wm * 64 + mi * 16 + (lane & 15);
                int gA = 2 * ks + (lane >> 4);
                ldm4(af[mi], swadr(sa + OA, rA, gA));
            }
            #pragma unroll
            for (int bi = 0; bi < 2; bi++) {
                int rB = wn * 32 + bi * 16 + (lane & 7) + ((lane >> 4) << 3);
                int gB = 2 * ks + ((lane >> 3) & 1);
                ldm4(bh[bi], swadr(sa + OBH, rB, gB));
                ldm4(bl[bi], swadr(sa + OBL, rB, gB));
            }
            #pragma unroll
            for (int mi = 0; mi < 4; mi++)
                #pragma unroll
                for (int nf = 0; nf < 4; nf++)
                    mma16816(acc[mi][nf], af[mi], &bh[nf >> 1][(nf & 1) * 2]);
            #pragma unroll
            for (int mi = 0; mi < 4; mi++)
                #pragma unroll
                for (int nf = 0; nf < 4; nf++)
                    mma16816(acc[mi][nf], af[mi], &bl[nf >> 1][(nf & 1) * 2]);
        }
        __syncthreads();
    }

    // ---- epilogue
    #pragma unroll
    for (int mi = 0; mi < 4; mi++) {
        #pragma unroll
        for (int nf = 0; nf < 4; nf++) {
            int r0  = bm + wm * 64 + mi * 16 + (lane >> 2);
            int col = n0 + wn * 32 + nf * 8 + ((lane & 3) << 1);
            float2 b2 = *(const float2*)&bias[col];
            float v0 = acc[mi][nf][0] + b2.x;
            float v1 = acc[mi][nf][1] + b2.y;
            float v2 = acc[mi][nf][2] + b2.x;
            float v3 = acc[mi][nf][3] + b2.y;
            if (r0 < M) {
                size_t o = (size_t)r0 * Ntot + col;
                if (C)  *(float2*)&C[o] = make_float2(v0, v1);
                if (Ch) *(uint32_t*)&Ch[o] =
                    packh(__float2half_rn(v0), __float2half_rn(v1));
            }
            if (r0 + 8 < M) {
                size_t o = (size_t)(r0 + 8) * Ntot + col;
                if (C)  *(float2*)&C[o] = make_float2(v2, v3);
                if (Ch) *(uint32_t*)&Ch[o] =
                    packh(__float2half_rn(v2), __float2half_rn(v3));
            }
        }
    }
}

// ---------------------------------------------------------------------------
// Weight prep: coalesced transpose W[256, N] -> rows [N,256], fp16 hi/lo
// grid.x = N/32; block 256
// ---------------------------------------------------------------------------
__global__ void prep_w(const float* __restrict__ W,
                       __half* __restrict__ hi,
                       __half* __restrict__ lo, int N)
{
    __shared__ float tile[256][33];
    const int n0 = blockIdx.x * 32;
    const int tx = threadIdx.x & 31;       // n within tile
    const int ty = threadIdx.x >> 5;       // 0..7
    for (int k = ty; k < 256; k += 8)
        tile[k][tx] = W[(size_t)k * N + n0 + tx];
    __syncthreads();
    // each warp writes 4 n-rows
    for (int nr = ty * 4; nr < ty * 4 + 4; nr++) {
        for (int k = tx; k < 256; k += 32) {
            float v = tile[k][nr];
            __half h = __float2half_rn(v);
            hi[(size_t)(n0 + nr) * 256 + k] = h;
            lo[(size_t)(n0 + nr) * 256 + k] = __float2half_rn(v - __half2float(h));
        }
    }
}

// ---------------------------------------------------------------------------
// split x -> fp16 (vectorized)
// ---------------------------------------------------------------------------
__global__ void split_x(const float* __restrict__ x,
                        __half* __restrict__ xh, int total4)
{
    int i = blockIdx.x * blockDim.x + threadIdx.x;
    if (i >= total4) return;
    float4 v = *(const float4*)&x[i * 4];
    uint2 p;
    p.x = packh(__float2half_rn(v.x), __float2half_rn(v.y));
    p.y = packh(__float2half_rn(v.z), __float2half_rn(v.w));
    *(uint2*)&xh[i * 4] = p;
}

// ---------------------------------------------------------------------------
// Attention: one block per node, warp per head (8 heads x 32 = 256 threads)
// ---------------------------------------------------------------------------
__global__ void attn_kernel(const float* __restrict__ xfq,   // q at col 256+
                            const __half* __restrict__ kkvv, // k col 0, v col 256
                            __half* __restrict__ out,
                            int s0)
{
    const int node = blockIdx.x;
    const int d = threadIdx.x;
    const float qv = xfq[(size_t)(s0 + node) * 512 + 256 + d];

    float logit[4];
    #pragma unroll
    for (int k = 0; k < 4; k++) {
        float p = qv * __half2float(kkvv[((size_t)(node * 4 + k)) * 512 + d]);
        #pragma unroll
        for (int off = 16; off > 0; off >>= 1)
            p += __shfl_xor_sync(0xffffffffu, p, off);
        logit[k] = p * 0.1767766952966369f;   // 1/sqrt(32)
    }
    float mx = fmaxf(fmaxf(logit[0], logit[1]), fmaxf(logit[2], logit[3]));
    float e[4];
    float s = 0.f;
    #pragma unroll
    for (int k = 0; k < 4; k++) { e[k] = expf(logit[k] - mx); s += e[k]; }
    const float inv = 1.f / s;

    float o = 0.f;
    #pragma unroll
    for (int k = 0; k < 4; k++)
        o += (e[k] * inv) * __half2float(kkvv[((size_t)(node * 4 + k)) * 512 + 256 + d]);
    out[(size_t)node * 256 + d] = __float2half_rn(o);
}

// ---------------------------------------------------------------------------
// Elementwise
// ---------------------------------------------------------------------------
__device__ __forceinline__ float sigm(float x) { return 1.f / (1.f + expf(-x)); }

__global__ void leaf_kernel(const float* __restrict__ xiou,
                            float* __restrict__ h_out,
                            float* __restrict__ c_out,
                            __half* __restrict__ hh)
{
    const size_t node = LEAF_S + (size_t)blockIdx.x * 4 + (threadIdx.x >> 6);
    const int j = (threadIdx.x & 63) << 2;
    const float4 i4 = *(const float4*)&xiou[node * 768 + j];
    const float4 o4 = *(const float4*)&xiou[node * 768 + 256 + j];
    const float4 u4 = *(const float4*)&xiou[node * 768 + 512 + j];
    float4 c, h;
    c.x = sigm(i4.x) * tanhf(u4.x); h.x = sigm(o4.x) * tanhf(c.x);
    c.y = sigm(i4.y) * tanhf(u4.y); h.y = sigm(o4.y) * tanhf(c.y);
    c.z = sigm(i4.z) * tanhf(u4.z); h.z = sigm(o4.z) * tanhf(c.z);
    c.w = sigm(i4.w) * tanhf(u4.w); h.w = sigm(o4.w) * tanhf(c.w);
    *(float4*)&h_out[node * 256 + j] = h;
    *(float4*)&c_out[node * 256 + j] = c;
    uint2 p;
    p.x = packh(__float2half_rn(h.x), __float2half_rn(h.y));
    p.y = packh(__float2half_rn(h.z), __float2half_rn(h.w));
    *(uint2*)&hh[node * 256 + j] = p;
}

__global__ void combine_kernel(const float* __restrict__ xiou,
                               const float* __restrict__ xfq,
                               const float* __restrict__ hu,
                               float* __restrict__ h_out,
                               float* __restrict__ c_out,
                               __half* __restrict__ hh,
                               int s0, int child_start)
{
    const int i = blockIdx.x;
    const int j = threadIdx.x;
    const size_t gr = (size_t)(s0 + i);

    const float ig = xiou[gr * 768 + j]       + hu[(size_t)i * 1024 + j];
    const float og = xiou[gr * 768 + 256 + j] + hu[(size_t)i * 1024 + 256 + j];
    const float ug = xiou[gr * 768 + 512 + j] + hu[(size_t)i * 1024 + 512 + j];
    const float f  = sigm(xfq[gr * 512 + j]   + hu[(size_t)i * 1024 + 768 + j]);

    const size_t cb = (size_t)(child_start + i * 4) * 256 + j;
    const float csum = c_out[cb] + c_out[cb + 256] + c_out[cb + 512] + c_out[cb + 768];

    const float c = sigm(ig) * tanhf(ug) + f * csum;
    const float h = sigm(og) * tanhf(c);
    h_out[gr * 256 + j] = h;
    c_out[gr * 256 + j] = c;
    hh[gr * 256 + j] = __float2half_rn(h);
}

// ---------------------------------------------------------------------------
// Launch
// ---------------------------------------------------------------------------
extern "C" void kernel_launch(void* const* d_in, const int* in_sizes, int n_in,
                              void* d_out, int out_size)
{
    const float* x      = (const float*)d_in[0];
    const float* W_iou  = (const float*)d_in[1];
    const float* b_iou  = (const float*)d_in[2];
    const float* W_f    = (const float*)d_in[3];
    const float* b_f    = (const float*)d_in[4];
    const float* Wq     = (const float*)d_in[5];
    const float* bq     = (const float*)d_in[6];
    const float* Wk     = (const float*)d_in[7];
    const float* bk     = (const float*)d_in[8];
    const float* Wv     = (const float*)d_in[9];
    const float* bv     = (const float*)d_in[10];
    const float* Wl     = (const float*)d_in[11];
    const float* bl     = (const float*)d_in[12];
    const float* Uiou_w = (const float*)d_in[13];
    const float* Uiou_b = (const float*)d_in[14];
    const float* Uf_w   = (const float*)d_in[15];
    const float* Uf_b   = (const float*)d_in[16];

    float* h_out = (float*)d_out;
    float* c_out = h_out + (size_t)NN * 256;

    float *xiou, *xfq, *hu, *bias;
    __half *kkvv, *att, *hatt, *xh, *hh, *wthi, *wtlo;
    cudaGetSymbolAddress((void**)&xiou, g_xiou);
    cudaGetSymbolAddress((void**)&xfq,  g_xfq);
    cudaGetSymbolAddress((void**)&hu,   g_hu);
    cudaGetSymbolAddress((void**)&bias, g_bias);
    cudaGetSymbolAddress((void**)&kkvv, g_kkvv);
    cudaGetSymbolAddress((void**)&att,  g_att);
    cudaGetSymbolAddress((void**)&hatt, g_hatt);
    cudaGetSymbolAddress((void**)&xh,   g_xh);
    cudaGetSymbolAddress((void**)&hh,   g_hh);
    cudaGetSymbolAddress((void**)&wthi, g_wthi);
    cudaGetSymbolAddress((void**)&wtlo, g_wtlo);

    cudaFuncSetAttribute(gemm_f16, cudaFuncAttributeMaxDynamicSharedMemorySize, GSMEM);

    auto GEMM = [&](const __half* A, int wt, float* C, __half* Ch, int M, int Ntot) {
        dim3 grid((M + 127) / 128, Ntot / 128);
        gemm_f16<<<grid, 256, GSMEM>>>(A, wthi + (size_t)wt * 256,
                                       wtlo + (size_t)wt * 256,
                                       bias + wt, C, Ch, M, Ntot);
    };

    // ---- weight prep (coalesced transpose + fp16 hi/lo split) ----
    prep_w<<<24, 256>>>(W_iou,  wthi + (size_t)WT_IOU * 256,        wtlo + (size_t)WT_IOU * 256,        768);
    prep_w<<< 8, 256>>>(W_f,    wthi + (size_t)WT_FQ * 256,         wtlo + (size_t)WT_FQ * 256,         256);
    prep_w<<< 8, 256>>>(Wq,     wthi + (size_t)(WT_FQ + 256) * 256, wtlo + (size_t)(WT_FQ + 256) * 256, 256);
    prep_w<<< 8, 256>>>(Wk,     wthi + (size_t)WT_KV * 256,         wtlo + (size_t)WT_KV * 256,         256);
    prep_w<<< 8, 256>>>(Wv,     wthi + (size_t)(WT_KV + 256) * 256, wtlo + (size_t)(WT_KV + 256) * 256, 256);
    prep_w<<< 8, 256>>>(Wl,     wthi + (size_t)WT_L * 256,          wtlo + (size_t)WT_L * 256,          256);
    prep_w<<<24, 256>>>(Uiou_w, wthi + (size_t)WT_U * 256,          wtlo + (size_t)WT_U * 256,          768);
    prep_w<<< 8, 256>>>(Uf_w,   wthi + (size_t)(WT_U + 768) * 256,  wtlo + (size_t)(WT_U + 768) * 256,  256);

    // ---- bias concat (device-to-device async copies; graph-capturable) ----
    cudaMemcpyAsync(bias + WT_IOU,      b_iou,  768 * 4, cudaMemcpyDeviceToDevice, 0);
    cudaMemcpyAsync(bias + WT_FQ,       b_f,    256 * 4, cudaMemcpyDeviceToDevice, 0);
    cudaMemcpyAsync(bias + WT_FQ + 256, bq,     256 * 4, cudaMemcpyDeviceToDevice, 0);
    cudaMemcpyAsync(bias + WT_KV,       bk,     256 * 4, cudaMemcpyDeviceToDevice, 0);
    cudaMemcpyAsync(bias + WT_KV + 256, bv,     256 * 4, cudaMemcpyDeviceToDevice, 0);
    cudaMemcpyAsync(bias + WT_L,        bl,     256 * 4, cudaMemcpyDeviceToDevice, 0);
    cudaMemcpyAsync(bias + WT_U,        Uiou_b, 768 * 4, cudaMemcpyDeviceToDevice, 0);
    cudaMemcpyAsync(bias + WT_U + 768,  Uf_b,   256 * 4, cudaMemcpyDeviceToDevice, 0);

    // ---- split x, precompute GEMMs ----
    const int tot4 = NN * 256 / 4;
    split_x<<<(tot4 + 255) / 256, 256>>>(x, xh, tot4);
    GEMM(xh, WT_IOU, xiou, nullptr, NN, 768);
    GEMM(xh, WT_FQ,  xfq,  nullptr, NI, 512);

    // ---- leaf level ----
    leaf_kernel<<<LEAF_N / 4, 256>>>(xiou, h_out, c_out, hh);

    // ---- internal levels, bottom-up ----
    const int starts[9] = {0, 1, 5, 21, 85, 341, 1365, 5461, 21845};
    for (int l = 7; l >= 0; l--) {
        const int n  = 1 << (2 * l);
        const int s0 = starts[l];
        const int cs = starts[l + 1];
        const int nK = n * 4;
        const __half* chh = hh + (size_t)cs * 256;

        GEMM(chh, WT_KV, nullptr, kkvv, nK, 512);
        attn_kernel<<<n, 256>>>(xfq, kkvv, att, s0);
        GEMM(att, WT_L, nullptr, hatt, n, 256);
        GEMM(hatt, WT_U, hu, nullptr, n, 1024);
        combine_kernel<<<n, 256>>>(xiou, xfq, hu, h_out, c_out, hh, s0, cs);
    }
}